// round 6
// baseline (speedup 1.0000x reference)
#include <cuda_runtime.h>
#include <cuda_bf16.h>

// Problem constants
#define N_TOK 8192
#define D_DIM 2048
#define M_DIM 512
#define E_NUM 4
#define CAP   8704   // 128-aligned permuted-row capacity (8192 + 4*128)

// GEMM geometry
#define BK      32
#define SROW    80                       // padded smem row bytes (32 bf16 -> 80B stride)
#define PLANE   (128 * SROW)             // 10240 B per plane tile
#define STAGE   (4 * PLANE)              // Ahi, Alo, Bhi, Blo
#define DSMEM   (2 * STAGE)              // 81920 B double-buffered

// ---------------------------------------------------------------------------
// Device scratch (allocation-free rule: __device__ globals only)
// ---------------------------------------------------------------------------
__device__ int g_cnt[E_NUM];
__device__ int g_c2[E_NUM];
__device__ int g_off[E_NUM + 1];
__device__ int g_is64;
__device__ int g_ptok[CAP];

__device__ __align__(256) __nv_bfloat16 g_w1hi[(size_t)E_NUM * M_DIM * D_DIM];
__device__ __align__(256) __nv_bfloat16 g_w1lo[(size_t)E_NUM * M_DIM * D_DIM];
__device__ __align__(256) __nv_bfloat16 g_w2hi[(size_t)E_NUM * D_DIM * M_DIM];
__device__ __align__(256) __nv_bfloat16 g_w2lo[(size_t)E_NUM * D_DIM * M_DIM];
__device__ __align__(256) __nv_bfloat16 g_hhi[(size_t)CAP * M_DIM];
__device__ __align__(256) __nv_bfloat16 g_hlo[(size_t)CAP * M_DIM];

// ---------------------------------------------------------------------------
// Helpers
// ---------------------------------------------------------------------------
__device__ __forceinline__ void split2(float v, unsigned short& hi, unsigned short& lo) {
    __nv_bfloat16 h = __float2bfloat16(v);
    __nv_bfloat16 l = __float2bfloat16(v - __bfloat162float(h));
    hi = __bfloat16_as_ushort(h);
    lo = __bfloat16_as_ushort(l);
}
// packed: returns bf16(b)<<16 | bf16(a)
__device__ __forceinline__ unsigned bf16x2_of(float a, float b) {
    unsigned r;
    asm("cvt.rn.bf16x2.f32 %0, %1, %2;" : "=r"(r) : "f"(b), "f"(a));
    return r;
}
// split two floats into packed hi word + packed lo word
__device__ __forceinline__ void split_pair(float a, float b, unsigned& hw, unsigned& lw) {
    hw = bf16x2_of(a, b);
    float ah = __uint_as_float(hw << 16);
    float bh = __uint_as_float(hw & 0xFFFF0000u);
    lw = bf16x2_of(a - ah, b - bh);
}
__device__ __forceinline__ unsigned smem_to_u32(const void* p) {
    unsigned a;
    asm("{ .reg .u64 t; cvta.to.shared.u64 t, %1; cvt.u32.u64 %0, t; }" : "=r"(a) : "l"(p));
    return a;
}
__device__ __forceinline__ void cp16(unsigned dst, const void* src) {
    asm volatile("cp.async.cg.shared.global [%0], [%1], 16;" :: "r"(dst), "l"(src));
}
#define CP_COMMIT() asm volatile("cp.async.commit_group;" ::: "memory")
#define CP_WAIT1()  asm volatile("cp.async.wait_group 1;" ::: "memory")
#define CP_WAIT0()  asm volatile("cp.async.wait_group 0;" ::: "memory")

__device__ __forceinline__ void ldsm4(unsigned* r, unsigned addr) {
    asm volatile("ldmatrix.sync.aligned.m8n8.x4.shared.b16 {%0,%1,%2,%3}, [%4];"
                 : "=r"(r[0]), "=r"(r[1]), "=r"(r[2]), "=r"(r[3]) : "r"(addr));
}
__device__ __forceinline__ void mma16816(float* c, const unsigned* a, const unsigned* b) {
    asm volatile("mma.sync.aligned.m16n8k16.row.col.f32.bf16.bf16.f32 "
                 "{%0,%1,%2,%3},{%4,%5,%6,%7},{%8,%9},{%0,%1,%2,%3};"
                 : "+f"(c[0]), "+f"(c[1]), "+f"(c[2]), "+f"(c[3])
                 : "r"(a[0]), "r"(a[1]), "r"(a[2]), "r"(a[3]), "r"(b[0]), "r"(b[1]));
}

// ---------------------------------------------------------------------------
// Prep kernels
// ---------------------------------------------------------------------------
__global__ void prep0_kernel(const int* __restrict__ dom32) {
    int t = blockIdx.x * blockDim.x + threadIdx.x;
    if (t < CAP) g_ptok[t] = -1;
    if (t < E_NUM) { g_cnt[t] = 0; g_c2[t] = 0; }
    if (blockIdx.x == 0) {
        __shared__ int anynz;
        if (threadIdx.x == 0) anynz = 0;
        __syncthreads();
        for (int w = 1 + 2 * threadIdx.x; w < 512; w += 2 * blockDim.x)
            if (dom32[w] != 0) anynz = 1;
        __syncthreads();
        if (threadIdx.x == 0) g_is64 = (anynz == 0) ? 1 : 0;
    }
}
__device__ __forceinline__ int read_dom(const void* dom, int i) {
    int e = g_is64 ? (int)((const long long*)dom)[i] : ((const int*)dom)[i];
    return e & (E_NUM - 1);
}
__global__ void count_kernel(const void* __restrict__ dom) {
    int i = blockIdx.x * blockDim.x + threadIdx.x;
    if (i < N_TOK) atomicAdd(&g_cnt[read_dom(dom, i)], 1);
}
__global__ void offsets_kernel() {
    if (threadIdx.x == 0) {
        int off = 0;
        for (int e = 0; e < E_NUM; e++) {
            g_off[e] = off;
            off += ((g_cnt[e] + 127) / 128) * 128;
        }
        g_off[E_NUM] = off;
    }
}
__global__ void scatter_kernel(const void* __restrict__ dom) {
    int i = blockIdx.x * blockDim.x + threadIdx.x;
    if (i < N_TOK) {
        int e = read_dom(dom, i);
        int pos = g_off[e] + atomicAdd(&g_c2[e], 1);
        g_ptok[pos] = i;
    }
}

// Convert W1 and W2 into bf16 hi/lo planes (4 elems / thread)
__global__ void convert_w_kernel(const float* __restrict__ W1, const float* __restrict__ W2) {
    size_t i = (size_t)blockIdx.x * blockDim.x + threadIdx.x;
    const size_t n1 = (size_t)E_NUM * M_DIM * D_DIM / 4;
    const size_t n2 = (size_t)E_NUM * D_DIM * M_DIM / 4;
    const float4* src;
    uint2 *dh, *dl;
    size_t j;
    if (i < n1)           { src = (const float4*)W1; j = i;      dh = (uint2*)g_w1hi; dl = (uint2*)g_w1lo; }
    else if (i < n1 + n2) { src = (const float4*)W2; j = i - n1; dh = (uint2*)g_w2hi; dl = (uint2*)g_w2lo; }
    else return;
    float4 a = src[j];
    uint2 h, l;
    split_pair(a.x, a.y, h.x, l.x);
    split_pair(a.z, a.w, h.y, l.y);
    dh[j] = h;
    dl[j] = l;
}

// ---------------------------------------------------------------------------
// Shared GEMM compute core: one BK=32 chunk, 8 warps, warp tile 64x32,
// bf16x3 (hi*hi + hi*lo + lo*hi) into fp32 accumulators.
// Stage layout: plane0=Ahi, plane1=Alo, plane2=Bhi, plane3=Blo.
// ---------------------------------------------------------------------------
__device__ __forceinline__ void compute_chunk(
    unsigned S, float acc[4][4][4],
    int a_row, int a_kc0, int b_row, int b_kc0)
{
#pragma unroll
    for (int ks = 0; ks < 2; ks++) {
        unsigned a_hi[4][4], a_lo[4][4];
        const unsigned aoffb = (unsigned)(a_row * SROW + (ks * 16 + a_kc0) * 2);
#pragma unroll
        for (int mt = 0; mt < 4; mt++) {
            unsigned off = aoffb + mt * 16 * SROW;
            ldsm4(a_hi[mt], S + 0 * PLANE + off);
            ldsm4(a_lo[mt], S + 1 * PLANE + off);
        }
        unsigned b_hi[8], b_lo[8];
        const unsigned boffb = (unsigned)(b_row * SROW + (ks * 16 + b_kc0) * 2);
#pragma unroll
        for (int np = 0; np < 2; np++) {
            unsigned off = boffb + np * 16 * SROW;
            ldsm4(&b_hi[np * 4], S + 2 * PLANE + off);
            ldsm4(&b_lo[np * 4], S + 3 * PLANE + off);
        }
#pragma unroll
        for (int mt = 0; mt < 4; mt++)
#pragma unroll
            for (int nt = 0; nt < 4; nt++) {
                const unsigned* bh = &b_hi[(nt >> 1) * 4 + (nt & 1) * 2];
                const unsigned* bl = &b_lo[(nt >> 1) * 4 + (nt & 1) * 2];
                mma16816(acc[mt][nt], a_hi[mt], bh);
                mma16816(acc[mt][nt], a_hi[mt], bl);
                mma16816(acc[mt][nt], a_lo[mt], bh);
            }
    }
}

// B planes (hi,lo) prefetch via cp.async: 2 planes x 512 cp16 = 2 per thread/plane
__device__ __forceinline__ void prefetch_B(
    unsigned s0, const __nv_bfloat16* __restrict__ Bh,
    const __nv_bfloat16* __restrict__ Bl, int kchunk, int KS, int tid)
{
    const __nv_bfloat16* srcs[2] = {Bh, Bl};
#pragma unroll
    for (int pl = 0; pl < 2; pl++) {
        const __nv_bfloat16* sp = srcs[pl] + (size_t)kchunk * BK;
        unsigned d0 = s0 + (2 + pl) * PLANE;
#pragma unroll
        for (int t = 0; t < 2; t++) {
            int idx = tid + t * 256;
            int row = idx >> 2, c = idx & 3;
            cp16(d0 + row * SROW + c * 16, sp + (size_t)row * KS + c * 8);
        }
    }
}

// ---------------------------------------------------------------------------
// GEMM1: A = gathered fp32 x rows, split to bf16 hi/lo in registers (fused
// convert), B = W1 planes via cp.async. Writes h hi/lo planes.
// ---------------------------------------------------------------------------
__global__ __launch_bounds__(256, 1) void gemm1_kernel(
    const float* __restrict__ x, const float* __restrict__ b1)
{
    constexpr int KS = D_DIM;
    constexpr int NC = KS / BK;   // 64

    const int row0 = blockIdx.x * 128;
    if (row0 >= g_off[E_NUM]) return;
    int e = 0;
    while (e < E_NUM - 1 && row0 >= g_off[e + 1]) e++;
    const int col0 = blockIdx.y * 128;

    extern __shared__ char smem_raw[];
    const unsigned sbase = smem_to_u32(smem_raw);

    const int tid = threadIdx.x;
    const int wid = tid >> 5, lane = tid & 31;
    const int warp_m = wid >> 2, warp_n = wid & 3;

    const __nv_bfloat16* Bhi = g_w1hi + ((size_t)e * M_DIM + col0) * D_DIM;
    const __nv_bfloat16* Blo = g_w1lo + ((size_t)e * M_DIM + col0) * D_DIM;

    // A gather map: 1024 float4 slots (128 rows x 8), 4 per thread.
    int tokA[4], rowA[4], colA[4];
#pragma unroll
    for (int t = 0; t < 4; t++) {
        int idx = tid + t * 256;
        rowA[t] = idx >> 3;
        colA[t] = idx & 7;
        tokA[t] = g_ptok[row0 + rowA[t]];
    }

    float acc[4][4][4];
#pragma unroll
    for (int i = 0; i < 4; i++)
#pragma unroll
        for (int j = 0; j < 4; j++)
#pragma unroll
            for (int q = 0; q < 4; q++) acc[i][j][q] = 0.f;

    const int a_row = warp_m * 64 + (lane & 7) + ((lane >> 3) & 1) * 8;
    const int a_kc0 = ((lane >> 4) & 1) * 8;
    const int b_row = warp_n * 32 + (lane & 7) + ((lane >> 4) & 1) * 8;
    const int b_kc0 = ((lane >> 3) & 1) * 8;

    // register A loader (fp32 gather + split)
    uint2 hA[4], lA[4], hA2[4], lA2[4];
    auto ldgA = [&](int c, uint2* H, uint2* L) {
#pragma unroll
        for (int t = 0; t < 4; t++) {
            uint2 h = make_uint2(0, 0), l = make_uint2(0, 0);
            if (tokA[t] >= 0) {
                float4 v = *(const float4*)(x + (size_t)tokA[t] * D_DIM + c * BK + colA[t] * 4);
                split_pair(v.x, v.y, h.x, l.x);
                split_pair(v.z, v.w, h.y, l.y);
            }
            H[t] = h; L[t] = l;
        }
    };
    auto stsA = [&](unsigned s0, const uint2* H, const uint2* L) {
#pragma unroll
        for (int t = 0; t < 4; t++) {
            unsigned off = (unsigned)(rowA[t] * SROW + colA[t] * 8);
            asm volatile("st.shared.v2.b32 [%0], {%1,%2};"
                         :: "r"(s0 + 0 * PLANE + off), "r"(H[t].x), "r"(H[t].y) : "memory");
            asm volatile("st.shared.v2.b32 [%0], {%1,%2};"
                         :: "r"(s0 + 1 * PLANE + off), "r"(L[t].x), "r"(L[t].y) : "memory");
        }
    };

    ldgA(0, hA, lA);
    prefetch_B(sbase, Bhi, Blo, 0, KS, tid);
    CP_COMMIT();

    for (int c = 0; c < NC; c++) {
        const unsigned S = sbase + (c & 1) * STAGE;
        if (c + 1 < NC) {
            prefetch_B(sbase + ((c + 1) & 1) * STAGE, Bhi, Blo, c + 1, KS, tid);
            CP_COMMIT();
        }
        stsA(S, hA, lA);
        if (c + 1 < NC) {
            ldgA(c + 1, hA2, lA2);
            CP_WAIT1();
        } else {
            CP_WAIT0();
        }
        __syncthreads();
        compute_chunk(S, acc, a_row, a_kc0, b_row, b_kc0);
        __syncthreads();
#pragma unroll
        for (int t = 0; t < 4; t++) { hA[t] = hA2[t]; lA[t] = lA2[t]; }
    }

    // Epilogue: bias + ReLU -> h hi/lo planes
#pragma unroll
    for (int mt = 0; mt < 4; mt++) {
        const int prow = row0 + warp_m * 64 + mt * 16 + (lane >> 2);
#pragma unroll
        for (int half = 0; half < 2; half++) {
            const int p = prow + half * 8;
#pragma unroll
            for (int nt = 0; nt < 4; nt++) {
                const int ncol = col0 + warp_n * 32 + nt * 8 + (lane & 3) * 2;
                const float* bs = b1 + (size_t)e * M_DIM + ncol;
                float v0 = fmaxf(acc[mt][nt][half * 2 + 0] + bs[0], 0.f);
                float v1 = fmaxf(acc[mt][nt][half * 2 + 1] + bs[1], 0.f);
                unsigned hw, lw;
                split_pair(v0, v1, hw, lw);
                *(unsigned*)(g_hhi + (size_t)p * M_DIM + ncol) = hw;
                *(unsigned*)(g_hlo + (size_t)p * M_DIM + ncol) = lw;
            }
        }
    }
}

// ---------------------------------------------------------------------------
// GEMM2: A = h planes, B = W2 planes, all cp.async; 2 CTAs/SM target.
// ---------------------------------------------------------------------------
__device__ __forceinline__ void prefetch_A_planes(
    unsigned s0, const __nv_bfloat16* __restrict__ Ah,
    const __nv_bfloat16* __restrict__ Al, int kchunk, int KS, int tid)
{
    const __nv_bfloat16* srcs[2] = {Ah, Al};
#pragma unroll
    for (int pl = 0; pl < 2; pl++) {
        const __nv_bfloat16* sp = srcs[pl] + (size_t)kchunk * BK;
        unsigned d0 = s0 + pl * PLANE;
#pragma unroll
        for (int t = 0; t < 2; t++) {
            int idx = tid + t * 256;
            int row = idx >> 2, c = idx & 3;
            cp16(d0 + row * SROW + c * 16, sp + (size_t)row * KS + c * 8);
        }
    }
}

__global__ __launch_bounds__(256, 2) void gemm2_kernel(
    const float* __restrict__ x, const float* __restrict__ b2,
    float* __restrict__ out)
{
    constexpr int KS = M_DIM;
    constexpr int NC = KS / BK;   // 16

    const int row0 = blockIdx.x * 128;
    if (row0 >= g_off[E_NUM]) return;
    int e = 0;
    while (e < E_NUM - 1 && row0 >= g_off[e + 1]) e++;
    const int col0 = blockIdx.y * 128;

    extern __shared__ char smem_raw[];
    const unsigned sbase = smem_to_u32(smem_raw);

    const int tid = threadIdx.x;
    const int wid = tid >> 5, lane = tid & 31;
    const int warp_m = wid >> 2, warp_n = wid & 3;

    const __nv_bfloat16* Ahi = g_hhi + (size_t)row0 * KS;
    const __nv_bfloat16* Alo = g_hlo + (size_t)row0 * KS;
    const __nv_bfloat16* Bhi = g_w2hi + ((size_t)e * D_DIM + col0) * M_DIM;
    const __nv_bfloat16* Blo = g_w2lo + ((size_t)e * D_DIM + col0) * M_DIM;

    float acc[4][4][4];
#pragma unroll
    for (int i = 0; i < 4; i++)
#pragma unroll
        for (int j = 0; j < 4; j++)
#pragma unroll
            for (int q = 0; q < 4; q++) acc[i][j][q] = 0.f;

    const int a_row = warp_m * 64 + (lane & 7) + ((lane >> 3) & 1) * 8;
    const int a_kc0 = ((lane >> 4) & 1) * 8;
    const int b_row = warp_n * 32 + (lane & 7) + ((lane >> 4) & 1) * 8;
    const int b_kc0 = ((lane >> 3) & 1) * 8;

    prefetch_A_planes(sbase, Ahi, Alo, 0, KS, tid);
    prefetch_B(sbase, Bhi, Blo, 0, KS, tid);
    CP_COMMIT();

    for (int c = 0; c < NC; c++) {
        const unsigned S = sbase + (c & 1) * STAGE;
        if (c + 1 < NC) {
            unsigned Sn = sbase + ((c + 1) & 1) * STAGE;
            prefetch_A_planes(Sn, Ahi, Alo, c + 1, KS, tid);
            prefetch_B(Sn, Bhi, Blo, c + 1, KS, tid);
            CP_COMMIT();
            CP_WAIT1();
        } else {
            CP_WAIT0();
        }
        __syncthreads();
        compute_chunk(S, acc, a_row, a_kc0, b_row, b_kc0);
        __syncthreads();
    }

    // Epilogue: residual + bias -> out (scatter by token)
#pragma unroll
    for (int mt = 0; mt < 4; mt++) {
        const int prow = row0 + warp_m * 64 + mt * 16 + (lane >> 2);
#pragma unroll
        for (int half = 0; half < 2; half++) {
            const int p = prow + half * 8;
            const int tok = g_ptok[p];
            if (tok < 0) continue;
#pragma unroll
            for (int nt = 0; nt < 4; nt++) {
                const int ncol = col0 + warp_n * 32 + nt * 8 + (lane & 3) * 2;
                const float* xs = x + (size_t)tok * D_DIM + ncol;
                const float* bs = b2 + (size_t)e * D_DIM + ncol;
                float2 o;
                o.x = xs[0] + acc[mt][nt][half * 2 + 0] + bs[0];
                o.y = xs[1] + acc[mt][nt][half * 2 + 1] + bs[1];
                *(float2*)(out + (size_t)tok * D_DIM + ncol) = o;
            }
        }
    }
}

// ---------------------------------------------------------------------------
// Launch
// ---------------------------------------------------------------------------
extern "C" void kernel_launch(void* const* d_in, const int* in_sizes, int n_in,
                              void* d_out, int out_size) {
    const float* x   = (const float*)d_in[0];
    const void*  dom = d_in[1];
    const float* W1  = (const float*)d_in[2];
    const float* b1  = (const float*)d_in[3];
    const float* W2  = (const float*)d_in[4];
    const float* b2  = (const float*)d_in[5];
    float*       out = (float*)d_out;

    cudaFuncSetAttribute(gemm1_kernel, cudaFuncAttributeMaxDynamicSharedMemorySize, DSMEM);
    cudaFuncSetAttribute(gemm2_kernel, cudaFuncAttributeMaxDynamicSharedMemorySize, DSMEM);

    prep0_kernel<<<(CAP + 255) / 256, 256>>>((const int*)dom);
    count_kernel<<<N_TOK / 256, 256>>>(dom);
    offsets_kernel<<<1, 32>>>();
    scatter_kernel<<<N_TOK / 256, 256>>>(dom);
    {
        const size_t tot = (size_t)E_NUM * M_DIM * D_DIM / 4 * 2;  // W1 + W2 float4 units
        convert_w_kernel<<<(unsigned)((tot + 255) / 256), 256>>>(W1, W2);
    }
    gemm1_kernel<<<dim3(CAP / 128, M_DIM / 128), 256, DSMEM>>>(x, b1);
    gemm2_kernel<<<dim3(CAP / 128, D_DIM / 128), 256, DSMEM>>>(x, b2, out);
}